// round 17
// baseline (speedup 1.0000x reference)
#include <cuda_runtime.h>
#include <cuda_fp16.h>
#include <math.h>
#include <stdint.h>

// Shapes (fixed)
#define D_  1024
#define B_  128
#define T_  256

#define KSTAGE  128                   // k per stage (2 x 64k sub-tiles)
#define NSTAGES (D_ / KSTAGE)         // 8
#define A_STAGE 32768                 // A: 128 rows x 128 k fp16 (2 sub-tiles)
#define NBUF    3
#define A_PIPE  (NBUF * A_STAGE)      // 98304
#define B_RES   A_PIPE                // B resident: 16 sub-tiles x 4KB
#define SMEM_DYN (A_PIPE + 16 * 4096) // 163840 = 160 KB, 1 CTA/SM

#define NCTA    128                   // one n-tile (N=32) per CTA, M=128
#define NTHREADS 512                  // 16 warps = 4 m-warps x 4 kq-groups
#define CREG    18432u                // combine region stride (128*36*4)

// Device scratch (allocation-free). fp16 bits stored as ushort.
__device__ unsigned short g_WcT[4 * D_ * D_];     // combined W^T fp16 [n][k]
__device__ unsigned short g_W1T[4 * D_ * D_];     // step-1 W^T fp16
__device__ unsigned short g_hF[2][B_ * D_];       // h fp16 ping-pong
__device__ unsigned       g_ready[8];             // per-k-chunk arrive counters

// ---------------------------------------------------------------------------
// PTX helpers (plain sm_80+ features only)
// ---------------------------------------------------------------------------
__device__ __forceinline__ uint32_t s2u(const void* p) {
    uint32_t a;
    asm("{ .reg .u64 t; cvta.to.shared.u64 t, %1; cvt.u32.u64 %0, t; }"
        : "=r"(a) : "l"(p));
    return a;
}
__device__ __forceinline__ void cpasync16(uint32_t dst, const void* src) {
    asm volatile("cp.async.cg.shared.global [%0], [%1], 16;" :: "r"(dst), "l"(src));
}
__device__ __forceinline__ void cp_commit() {
    asm volatile("cp.async.commit_group;" ::: "memory");
}
template <int N> __device__ __forceinline__ void cp_wait() {
    asm volatile("cp.async.wait_group %0;" :: "n"(N) : "memory");
}
__device__ __forceinline__ void ldsm4(uint32_t* r, uint32_t addr) {
    asm volatile("ldmatrix.sync.aligned.m8n8.x4.shared.b16 {%0,%1,%2,%3}, [%4];"
        : "=r"(r[0]), "=r"(r[1]), "=r"(r[2]), "=r"(r[3]) : "r"(addr));
}
__device__ __forceinline__ void mma_f16(float* c, const uint32_t* a,
                                        uint32_t b0, uint32_t b1) {
    asm volatile("mma.sync.aligned.m16n8k16.row.col.f32.f16.f16.f32 "
        "{%0,%1,%2,%3}, {%4,%5,%6,%7}, {%8,%9}, {%0,%1,%2,%3};"
        : "+f"(c[0]), "+f"(c[1]), "+f"(c[2]), "+f"(c[3])
        : "r"(a[0]), "r"(a[1]), "r"(a[2]), "r"(a[3]), "r"(b0), "r"(b1));
}
__device__ __forceinline__ uint32_t sw128(uint32_t off) {
    return off ^ ((off >> 3) & 0x70);
}
__device__ __forceinline__ void poll_ge(volatile unsigned* p, unsigned target) {
    while (*p < target) { }
}

// ---------------------------------------------------------------------------
// Merged prologue: weights transform (fp16) + x0 + counter reset.
// ---------------------------------------------------------------------------
__global__ void prep_all(const float* __restrict__ Wk,
                         const float* __restrict__ Wr,
                         const float* __restrict__ x,
                         float* __restrict__ out) {
    int i = blockIdx.x * blockDim.x + threadIdx.x;
    {   // ---- weights: [n][k] transposed, gates {Wz+Rz, Wr+Rr, Wh, Rh} ----
        int n  = i >> 7;
        int k0 = (i & 127) * 8;
        int d = n >> 2, g = n & 3;
        long o = (long)n * D_ + k0;
        #pragma unroll
        for (int j = 0; j < 8; j++) {
            long src = (long)(k0 + j) * (3 * D_) + (long)g * D_ + d;
            float wc, w1;
            if (g == 3) {
                float rh = Wr[(long)(k0 + j) * (3 * D_) + 2 * D_ + d];
                wc = rh; w1 = 0.f;
            } else {
                float a = Wk[src];
                float b = Wr[src];
                w1 = a;
                wc = (g == 2) ? a : (a + b);
            }
            g_WcT[o + j] = __half_as_ushort(__float2half_rn(wc));
            g_W1T[o + j] = __half_as_ushort(__float2half_rn(w1));
        }
    }
    if (i < 8) g_ready[i] = 0u;
    if (i < B_ * D_) {   // ---- x0: out[:,0,:] = x0; fp16 into h buf 0 ----
        int b = i >> 10, d = i & (D_ - 1);
        float v = x[(long)b * D_ + d];
        out[(long)b * (T_ * D_) + d] = v;
        g_hF[0][i] = __half_as_ushort(__float2half_rn(v));
    }
}

// ---------------------------------------------------------------------------
// Loaders (512 threads, coalesced)
// ---------------------------------------------------------------------------
// A stage: 2 sub-tiles x (128 rows x 64 k fp16, 128B rows) = 32 KB.
__device__ __forceinline__ void load_A(
    uint32_t st, int k0, const unsigned short* Ah, int tid)
{
    #pragma unroll
    for (int t = 0; t < 4; t++) {
        int r   = t * 512 + tid;            // 0..2047 16B-chunks
        int sub = r >> 10;                  // sub-tile 0/1
        int rr  = r & 1023;
        int row = rr >> 3, ch = rr & 7;
        uint32_t sw = sw128((uint32_t)(row * 128 + ch * 16));
        const long ko = (long)k0 + sub * 64 + ch * 8;
        cpasync16(st + (uint32_t)sub * 16384 + sw, Ah + (long)row * D_ + ko);
    }
}
// B resident (fp16): 16 sub-tiles x (32 rows x 64 k) = 64 KB.
__device__ __forceinline__ void load_B_res(
    uint32_t sbase, const unsigned short* Bw, int nrow0, int tid)
{
    #pragma unroll
    for (int t = 0; t < 8; t++) {
        int r   = t * 512 + tid;            // 4096 chunks total
        int s   = r >> 8;                   // sub-tile
        int rr  = r & 255;
        int row = rr >> 3, ch = rr & 7;
        uint32_t dst = sbase + B_RES + (uint32_t)s * 4096;
        uint32_t sw = sw128((uint32_t)(row * 128 + ch * 16));
        const long ko = (long)s * 64 + ch * 8;
        cpasync16(dst + sw, Bw + (long)(nrow0 + row) * D_ + ko);
    }
}

// ---------------------------------------------------------------------------
// Persistent GRU: 255 steps; per-k-chunk producer counters instead of a
// global barrier. CTA nb produces h cols [nb*8, nb*8+8) = chunk nb>>4; it
// processes k-stages rotated to start at its own chunk, so its first wait
// is on 15 peer CTAs and later chunks are long since ready. Consumers poll
// (tid 0) BEFORE cp_wait so poll latency overlaps cp.async completion.
// Grid 128 CTAs (1/SM), M=128 x N=32, fp16 weights resident, 1-MMA fp16
// mainloop (R16), distributed combine + epilogue; out stores post-arrive.
// ---------------------------------------------------------------------------
extern __shared__ char dsm[];

__global__ __launch_bounds__(NTHREADS, 1)
void gru_persist(const unsigned short* __restrict__ WcT,
                 const unsigned short* __restrict__ W1T,
                 const float* __restrict__ bias,
                 float* __restrict__ out,
                 unsigned short* __restrict__ hF)
{
    const uint32_t sbase = s2u(dsm);
    const int tid  = threadIdx.x;
    const int wid  = tid >> 5, lane = tid & 31;
    const int wk   = wid >> 2;                      // kq-group 0..3
    const int wm   = wid & 3;                       // m-warp (32 rows each)
    const int nb   = blockIdx.x;                    // n-tile (N=32)
    const int nrow0 = nb * 32;
    const int cb   = nb >> 4;                       // chunk this CTA produces

    // per-lane ldmatrix geometry
    const int fr   = (lane & 7) + ((lane >> 3) & 1) * 8;
    const int fch  = (lane >> 4) * 16;
    const uint32_t swz = (uint32_t)(lane & 7) << 4;
    const int subk = wk >> 1;                       // sub-tile within stage
    const int kc0  = (wk & 1) * 2;                  // first k16 chunk in sub

    // distributed-epilogue coordinates: each thread owns (erow, d2..d2+1)
    const int erow = tid >> 2;                      // 0..127
    const int ed0  = (tid & 3) * 2;                 // local d: ed0, ed0+1
    const int dg0  = nb * 8 + ed0;                  // global d base

    float bzv[2], brv[2], bhv[2];
    #pragma unroll
    for (int q = 0; q < 2; q++) {
        bzv[q] = bias[dg0 + q];
        brv[q] = bias[D_ + dg0 + q];
        bhv[q] = bias[2 * D_ + dg0 + q];
    }

    // ---- prime for t = 1: B-resident = W1, A stages sigma(0), sigma(1) ----
    const unsigned short* Ah = hF;
    load_B_res(sbase, W1T, nrow0, tid);
    cp_commit();
    load_A(sbase,           (cb & 7) * KSTAGE,       Ah, tid); cp_commit();
    load_A(sbase + A_STAGE, ((cb + 1) & 7) * KSTAGE, Ah, tid); cp_commit();

    float hold[2] = {0.f, 0.f};                     // h0 = 0

    for (int t = 1; t < T_; t++) {
        const bool last = (t == T_ - 1);
        const unsigned lvl = 16u * (unsigned)(t - 1);

        float acc[2][4][4];
        #pragma unroll
        for (int i = 0; i < 2; i++)
            #pragma unroll
            for (int j = 0; j < 4; j++)
                #pragma unroll
                for (int q = 0; q < 4; q++) acc[i][j][q] = 0.f;

        int buf = 0;
        for (int s = 0; s < NSTAGES; s++) {
            // poll producers of the chunk we are about to prefetch
            if (tid == 0 && s + 2 < NSTAGES)
                poll_ge(&g_ready[(s + 2 + cb) & 7], lvl);
            if (s < NSTAGES - 1) cp_wait<1>();
            else                 cp_wait<0>();
            __syncthreads();

            // refill stage sigma(s+2) into buf (s+2)%3 — freed at stage s-1
            if (s + 2 < NSTAGES) {
                int nxt = buf + 2; if (nxt >= NBUF) nxt -= NBUF;
                load_A(sbase + (uint32_t)nxt * A_STAGE,
                       ((s + 2 + cb) & 7) * KSTAGE, Ah, tid);
                cp_commit();
            }

            const int ss = (s + cb) & 7;            // rotated k-stage
            const uint32_t aT = sbase + (uint32_t)buf * A_STAGE
                              + (uint32_t)subk * 16384;
            const uint32_t bT = sbase + B_RES
                              + (uint32_t)(ss * 2 + subk) * 4096;

            #pragma unroll
            for (int kc = 0; kc < 2; kc++) {
                const uint32_t c = (uint32_t)((kc0 + kc) * 32 + fch) ^ swz;
                uint32_t ah[2][4], bb[2][4];
                #pragma unroll
                for (int mt = 0; mt < 2; mt++) {
                    uint32_t ro = (uint32_t)((wm * 32 + mt * 16 + fr) * 128) + c;
                    ldsm4(ah[mt], aT + ro);
                }
                #pragma unroll
                for (int np = 0; np < 2; np++) {
                    uint32_t ro = (uint32_t)((np * 16 + fr) * 128) + c;
                    ldsm4(bb[np], bT + ro);
                }
                #pragma unroll
                for (int mt = 0; mt < 2; mt++)
                    #pragma unroll
                    for (int nt = 0; nt < 4; nt++) {
                        const int np = nt >> 1, j = nt & 1;
                        mma_f16(acc[mt][nt], ah[mt], bb[np][j], bb[np][j + 2]);
                    }
            }
            buf = buf + 1; if (buf == NBUF) buf = 0;
        }

        // -------- all groups dump partials to smem (A-pipe area idle) -----
        __syncthreads();                       // all warps done reading bufs
        {
            const uint32_t comb = sbase + (uint32_t)wk * CREG;
            #pragma unroll
            for (int mt = 0; mt < 2; mt++)
                #pragma unroll
                for (int nt = 0; nt < 4; nt++) {
                    int r0 = wm * 32 + mt * 16 + (lane >> 2);
                    int c0 = nt * 8 + 2 * (lane & 3);
                    uint32_t ad = comb + (uint32_t)((r0 * 36 + c0) << 2);
                    asm volatile("st.shared.v2.f32 [%0], {%1,%2};"
                                 :: "r"(ad), "f"(acc[mt][nt][0]), "f"(acc[mt][nt][1]));
                    asm volatile("st.shared.v2.f32 [%0], {%1,%2};"
                                 :: "r"(ad + 8 * 36 * 4),
                                    "f"(acc[mt][nt][2]), "f"(acc[mt][nt][3]));
                }
        }
        __syncthreads();

        // -------- distributed combine + GRU gates: 2 outputs / thread -----
        unsigned short* nh = hF + (size_t)(t & 1) * B_ * D_;
        float hv[2];
        {
            #pragma unroll
            for (int q = 0; q < 2; q++) {
                const int dl = ed0 + q;
                const uint32_t off = (uint32_t)((erow * 36 + dl * 4) << 2);
                float az = 0.f, ar = 0.f, ahs = 0.f, ags = 0.f;
                #pragma unroll
                for (int gq = 0; gq < 4; gq++) {
                    float p0, p1, p2, p3;
                    asm volatile("ld.shared.v4.f32 {%0,%1,%2,%3}, [%4];"
                                 : "=f"(p0), "=f"(p1), "=f"(p2), "=f"(p3)
                                 : "r"(sbase + (uint32_t)gq * CREG + off));
                    az += p0; ar += p1; ahs += p2; ags += p3;
                }
                float z  = 1.f / (1.f + __expf(-(az + bzv[q])));
                float rr = 1.f / (1.f + __expf(-(ar + brv[q])));
                float xc = ahs + bhv[q] + rr * ags;
                float e  = __expf(-2.f * xc);
                float cand = (1.f - e) / (1.f + e);
                float h = z * hold[q] + (1.f - z) * cand;
                hold[q] = h;
                hv[q] = h;
            }
            // h store FIRST — it is the only cross-CTA dependency
            uint32_t hw = (uint32_t)__half_as_ushort(__float2half_rn(hv[0]))
                        | ((uint32_t)__half_as_ushort(__float2half_rn(hv[1])) << 16);
            *(uint32_t*)(nh + (long)erow * D_ + dg0) = hw;
        }

        if (!last) {
            // ---- arrive on own chunk; wait only for sigma(0), sigma(1) ----
            __threadfence();
            __syncthreads();
            if (tid == 0) {
                atomicAdd(&g_ready[cb], 1u);
                const unsigned lvl2 = 16u * (unsigned)t;
                poll_ge(&g_ready[cb], lvl2);             // sigma(0) = own
                poll_ge(&g_ready[(cb + 1) & 7], lvl2);   // sigma(1)
            }
            __syncthreads();

            Ah = nh;
            if (t == 1) {                 // switch resident weights to Wc
                load_B_res(sbase, WcT, nrow0, tid);
                cp_commit();
            }
            load_A(sbase,           (cb & 7) * KSTAGE,       Ah, tid); cp_commit();
            load_A(sbase + A_STAGE, ((cb + 1) & 7) * KSTAGE, Ah, tid); cp_commit();
        }

        // out stores off the critical path (post-arrive)
        {
            float* po = out + (long)erow * (T_ * D_) + (long)t * D_ + dg0;
            *(float2*)po = make_float2(hv[0], hv[1]);
        }
    }
}

// ---------------------------------------------------------------------------
extern "C" void kernel_launch(void* const* d_in, const int* in_sizes, int n_in,
                              void* d_out, int out_size) {
    const float* x    = (const float*)d_in[0];
    const float* Wk   = (const float*)d_in[1];
    const float* Wr   = (const float*)d_in[2];
    const float* bias = (const float*)d_in[3];
    float* out = (float*)d_out;

    unsigned short *WcT, *W1T, *hF;
    cudaGetSymbolAddress((void**)&WcT, g_WcT);
    cudaGetSymbolAddress((void**)&W1T, g_W1T);
    cudaGetSymbolAddress((void**)&hF,  g_hF);

    cudaFuncSetAttribute(gru_persist,
                         cudaFuncAttributeMaxDynamicSharedMemorySize, SMEM_DYN);

    prep_all<<<2048, 256>>>(Wk, Wr, x, out);   // also resets g_ready[]

    gru_persist<<<NCTA, NTHREADS, SMEM_DYN>>>(WcT, W1T, bias, out, hF);
}